// round 7
// baseline (speedup 1.0000x reference)
#include <cuda_runtime.h>
#include <cuda_bf16.h>
#include <math_constants.h>

// Problem shape (fixed by the dataset):
//   z_latents:  [128,32,32,64] f32  -> N = 131072 rows, D = 64
//   embeddings: [64,1024]      f32  -> D = 64, K = 1024
// Output: quantized_st (8388608 f32) then vq_loss (1 f32) -> 8388609 elements.

#define N_ROWS   131072
#define DIM      64
#define KCODES   1024
#define KCHUNK   128
#define THREADS  256
#define ROWS_PER_CTA 256
#define NBLOCKS  (N_ROWS / ROWS_PER_CTA)   // 512

// Scratch (no allocations allowed):
__device__ float  g_cbT[KCODES * DIM];     // codebook transposed [K][D] for row gather
__device__ float  g_se[KCODES];            // sum_d e[d][k]^2 (square-then-add, ascending d)
__device__ double g_partials[NBLOCKS];     // per-CTA loss partial sums

// ---------------- packed f32x2 helpers ----------------
__device__ __forceinline__ unsigned long long pk2(float lo, float hi) {
    unsigned long long r;
    asm("mov.b64 %0, {%1, %2};" : "=l"(r) : "f"(lo), "f"(hi));
    return r;
}
__device__ __forceinline__ void upk2(unsigned long long v, float& lo, float& hi) {
    asm("mov.b64 {%0, %1}, %2;" : "=f"(lo), "=f"(hi) : "l"(v));
}
__device__ __forceinline__ unsigned long long ffma2(unsigned long long a,
                                                    unsigned long long b,
                                                    unsigned long long c) {
    unsigned long long d;
    asm("fma.rn.f32x2 %0, %1, %2, %3;" : "=l"(d) : "l"(a), "l"(b), "l"(c));
    return d;
}

// ---------------- prep: transpose codebook + per-code squared norms ----------------
__global__ void vq_prep(const float* __restrict__ emb) {
    int k = blockIdx.x * blockDim.x + threadIdx.x;
    if (k < KCODES) {
        float s = 0.0f;
        #pragma unroll
        for (int d = 0; d < DIM; ++d) {
            float v = emb[d * KCODES + k];        // coalesced across k
            g_cbT[k * DIM + d] = v;
            s = __fadd_rn(s, __fmul_rn(v, v));    // square then add, ascending d
        }
        g_se[k] = s;
    }
}

// ---------------- main: distances + argmin + gather + ST output + loss partials ----
// dynamic smem layout:
//   zsm : ROWS_PER_CTA * 65 floats            (padded rows, 66560 B)
//   cbs : DIM * KCHUNK floats                 (32768 B, 16B-aligned)
//   ses : KCHUNK floats                       (512 B)
//   wsm : 8 doubles                           (64 B, 8B-aligned)
#define ZSM_FLOATS (ROWS_PER_CTA * 65)
#define CBS_OFF    ZSM_FLOATS
#define SES_OFF    (CBS_OFF + DIM * KCHUNK)
#define WSM_OFF_B  ((SES_OFF + KCHUNK) * 4)
#define SMEM_BYTES (WSM_OFF_B + 8 * 8)

__global__ void __launch_bounds__(THREADS, 2)
vq_main(const float* __restrict__ z,
        const float* __restrict__ emb,
        float* __restrict__ out)
{
    extern __shared__ float smem[];
    float* zsm = smem;
    float* cbs = smem + CBS_OFF;
    float* ses = smem + SES_OFF;
    double* wsm = (double*)((char*)smem + WSM_OFF_B);

    const int b = blockIdx.x;
    const int t = threadIdx.x;

    // -- stage this CTA's 256 z rows into smem (coalesced), then into registers --
    const float* zg = z + (size_t)b * ROWS_PER_CTA * DIM;
    #pragma unroll 4
    for (int i = t; i < ROWS_PER_CTA * DIM; i += THREADS) {
        int r = i >> 6, d = i & 63;
        zsm[r * 65 + d] = zg[i];
    }
    __syncthreads();

    float zr[DIM];
    #pragma unroll
    for (int d = 0; d < DIM; ++d) zr[d] = zsm[t * 65 + d];   // (t+d)%32 banks: conflict-free

    // s_z: square then add, ascending d (matches sum(flat*flat, axis=1) elementwise+reduce)
    float sz = 0.0f;
    #pragma unroll
    for (int d = 0; d < DIM; ++d) sz = __fadd_rn(sz, __fmul_rn(zr[d], zr[d]));

    float best = CUDART_INF_F;
    int   bidx = 0;

    for (int k0 = 0; k0 < KCODES; k0 += KCHUNK) {
        __syncthreads();
        // load codebook chunk [d][kc] (coalesced 512B rows from gmem/L2)
        #pragma unroll 4
        for (int i = t; i < DIM * KCHUNK; i += THREADS) {
            int d = i >> 7, kc = i & (KCHUNK - 1);
            cbs[i] = emb[d * KCODES + k0 + kc];
        }
        if (t < KCHUNK) ses[t] = g_se[k0 + t];
        __syncthreads();

        const ulonglong2* cb2base = (const ulonglong2*)cbs;  // 32 ulonglong2 per d-row

        for (int kc = 0; kc < KCHUNK; kc += 8) {
            const ulonglong2* cb2 = cb2base + (kc >> 2);
            unsigned long long a0 = 0ull, a1 = 0ull, a2 = 0ull, a3 = 0ull;
            #pragma unroll
            for (int d = 0; d < DIM; ++d) {
                ulonglong2 e0 = cb2[d * (KCHUNK / 4)];       // codes kc..kc+3 (broadcast LDS.128)
                ulonglong2 e1 = cb2[d * (KCHUNK / 4) + 1];   // codes kc+4..kc+7
                unsigned long long zz = pk2(zr[d], zr[d]);
                a0 = ffma2(zz, e0.x, a0);                    // exact sequential fp32 fma per code
                a1 = ffma2(zz, e0.y, a1);
                a2 = ffma2(zz, e1.x, a2);
                a3 = ffma2(zz, e1.y, a3);
            }
            float dot[8];
            upk2(a0, dot[0], dot[1]);
            upk2(a1, dot[2], dot[3]);
            upk2(a2, dot[4], dot[5]);
            upk2(a3, dot[6], dot[7]);
            #pragma unroll
            for (int j = 0; j < 8; ++j) {
                // dist = (s_z - 2*dot) + s_e  -- exact fp32, no contraction
                float dist = __fadd_rn(__fsub_rn(sz, __fmul_rn(2.0f, dot[j])), ses[kc + j]);
                if (dist < best) { best = dist; bidx = k0 + kc + j; }   // first-occurrence tie-break
            }
        }
    }

    // -- gather chosen code row, straight-through output, loss partial --
    double lsum = 0.0;
    const float4* qrow = (const float4*)(g_cbT + (size_t)bidx * DIM);
    float4* orow = (float4*)(out + ((size_t)b * ROWS_PER_CTA + t) * DIM);
    #pragma unroll
    for (int j = 0; j < DIM / 4; ++j) {
        float4 q4 = qrow[j];
        float4 o4;
        float z0 = zr[4*j+0], z1 = zr[4*j+1], z2 = zr[4*j+2], z3 = zr[4*j+3];
        float d0 = __fsub_rn(q4.x, z0);  o4.x = __fadd_rn(z0, d0);
        float d1 = __fsub_rn(q4.y, z1);  o4.y = __fadd_rn(z1, d1);
        float d2 = __fsub_rn(q4.z, z2);  o4.z = __fadd_rn(z2, d2);
        float d3 = __fsub_rn(q4.w, z3);  o4.w = __fadd_rn(z3, d3);
        lsum += (double)__fmul_rn(d0, d0) + (double)__fmul_rn(d1, d1)
              + (double)__fmul_rn(d2, d2) + (double)__fmul_rn(d3, d3);
        orow[j] = o4;
    }

    // deterministic block reduction of lsum (double)
    #pragma unroll
    for (int o = 16; o > 0; o >>= 1)
        lsum += __shfl_down_sync(0xffffffffu, lsum, o);
    if ((t & 31) == 0) wsm[t >> 5] = lsum;
    __syncthreads();
    if (t == 0) {
        double s = 0.0;
        #pragma unroll
        for (int w = 0; w < THREADS / 32; ++w) s += wsm[w];
        g_partials[b] = s;
    }
}

// ---------------- finish: reduce partials, emit vq_loss ----------------
__global__ void vq_finish(float* __restrict__ out) {
    __shared__ double sm[256];
    int t = threadIdx.x;
    sm[t] = g_partials[t] + g_partials[t + 256];
    __syncthreads();
    #pragma unroll
    for (int s = 128; s > 0; s >>= 1) {
        if (t < s) sm[t] += sm[t + s];
        __syncthreads();
    }
    if (t == 0) {
        float L = (float)(sm[0] / (double)(N_ROWS * DIM));
        // vq_loss = embedding_loss + 0.25 * commitment_loss, both equal L numerically
        out[N_ROWS * DIM] = __fadd_rn(L, __fmul_rn(0.25f, L));
    }
}

extern "C" void kernel_launch(void* const* d_in, const int* in_sizes, int n_in,
                              void* d_out, int out_size) {
    const float* z   = (const float*)d_in[0];
    const float* emb = (const float*)d_in[1];
    float* out = (float*)d_out;

    (void)in_sizes; (void)n_in; (void)out_size;

    cudaFuncSetAttribute(vq_main, cudaFuncAttributeMaxDynamicSharedMemorySize, SMEM_BYTES);

    vq_prep<<<(KCODES + 255) / 256, 256>>>(emb);
    vq_main<<<NBLOCKS, THREADS, SMEM_BYTES>>>(z, emb, out);
    vq_finish<<<1, 256>>>(out);
}